// round 6
// baseline (speedup 1.0000x reference)
#include <cuda_runtime.h>

#define NB 2
#define NS 2048
#define NE 1024
#define NH 16
#define ND 64
#define SC 64       // s-chunks for pv partials
#define SCLEN 32    // s per chunk (SC*SCLEN == NS)
#define NQ 4        // e-quarters for score partials

// Scratch (allocation-free: device globals)
__device__ float g_q[NB*NE];
__device__ float g_qwk[NB*NH*NE];        // [b][h][e]
__device__ float g_p[NQ*NB*NH*NS];       // raw score partials [q][b][h][s]
__device__ float g_pvp[NB*SC*NH*NE];     // unnormalized pv partials [b][sc][h][e] (8 MB)
__device__ float g_sump[NB*SC*NH];       // per-chunk exp sums
__device__ float g_pv[NB*NH*NE];
__device__ float g_o[NB*NE];
__device__ float g_y[NB*NE];

__device__ __forceinline__ float dot4(float4 a, float4 b){
  return fmaf(a.x,b.x, fmaf(a.y,b.y, fmaf(a.z,b.z, a.w*b.w)));
}
__device__ __forceinline__ float warp_sum(float v){
#pragma unroll
  for (int o=16;o>0;o>>=1) v += __shfl_xor_sync(0xffffffffu, v, o);
  return v;
}

// K1: g_q[b][j] = dot(inputs[b, S-1, :], Wq[j, :])  (warp per output, 256 blocks)
__global__ void k_q(const float* __restrict__ inputs, const float* __restrict__ Wq){
  int gw = (blockIdx.x*blockDim.x + threadIdx.x) >> 5;
  int lane = threadIdx.x & 31;
  int b = gw >> 10, j = gw & 1023;
  const float4* xr = (const float4*)(inputs + ((size_t)b*NS + (NS-1))*NE);
  const float4* wr = (const float4*)(Wq + (size_t)j*NE);
  float acc = 0.f;
#pragma unroll
  for (int it=0; it<8; ++it) acc += dot4(xr[lane+it*32], wr[lane+it*32]);
  acc = warp_sum(acc);
  if (!lane) g_q[b*NE+j] = acc;
}

// K2: g_qwk[b][h][e] = sum_d g_q[b][h*64+d] * Wk[h*64+d][e]
__global__ void __launch_bounds__(64) k_qwk(const float* __restrict__ Wk){
  int h = blockIdx.x >> 2, eq = blockIdx.x & 3, b = blockIdx.y;
  __shared__ float qs[ND];
  int t = threadIdx.x;
  qs[t] = g_q[b*NE + h*ND + t];
  __syncthreads();
  int e4 = eq*64 + t;
  const float4* Wk4 = (const float4*)Wk;
  float4 a = make_float4(0.f,0.f,0.f,0.f);
#pragma unroll 8
  for (int d=0; d<ND; ++d){
    float qv = qs[d];
    float4 w = Wk4[(size_t)(h*ND + d)*256 + e4];
    a.x = fmaf(qv,w.x,a.x); a.y = fmaf(qv,w.y,a.y);
    a.z = fmaf(qv,w.z,a.z); a.w = fmaf(qv,w.w,a.w);
  }
  ((float4*)g_qwk)[(size_t)(b*NH + h)*256 + e4] = a;
}

// K3: score e-quarter partials.
// Grid (NS/32, NQ, NB) = 512 blocks. Block 256 thr = 8 warps x 4 s-rows.
// g_p[q][b][h][s] = dot(embK[b,s,eq*256:(eq+1)*256], qwk[b,h,same])
__global__ void __launch_bounds__(256) k_scores(const float* __restrict__ embK){
  __shared__ float4 qwk_s[NH*64];      // 16 KB e-quarter
  int eq = blockIdx.y, b = blockIdx.z;
  {
    const float4* src = (const float4*)g_qwk + (size_t)b*NH*256 + eq*64;
#pragma unroll
    for (int i=0;i<4;i++){
      int idx = threadIdx.x + i*256;   // over 1024 = 16h x 64f4
      int h = idx >> 6, f4 = idx & 63;
      qwk_s[idx] = src[(size_t)h*256 + f4];
    }
  }
  __syncthreads();
  int wid = threadIdx.x >> 5, lane = threadIdx.x & 31;
  int s = blockIdx.x*32 + wid*4;
  const float4* r = (const float4*)(embK + ((size_t)b*NS + s)*NE) + eq*64;
  float acc[NH][4];
#pragma unroll
  for (int h=0;h<NH;h++){
#pragma unroll
    for (int k=0;k<4;k++) acc[h][k]=0.f;
  }
#pragma unroll
  for (int it=0; it<2; ++it){
    int e4 = lane + it*32;
    float4 x0 = r[e4];
    float4 x1 = r[e4 + 256];
    float4 x2 = r[e4 + 512];
    float4 x3 = r[e4 + 768];
#pragma unroll
    for (int h=0; h<NH; ++h){
      float4 w = qwk_s[h*64 + e4];
      acc[h][0] += dot4(x0,w);
      acc[h][1] += dot4(x1,w);
      acc[h][2] += dot4(x2,w);
      acc[h][3] += dot4(x3,w);
    }
  }
#pragma unroll
  for (int h=0;h<NH;h++){
#pragma unroll
    for (int k=0;k<4;k++) acc[h][k] = warp_sum(acc[h][k]);
  }
  if (!lane){
    float* dst = g_p + (size_t)eq*NB*NH*NS;
#pragma unroll
    for (int h=0;h<NH;h++){
#pragma unroll
      for (int k=0;k<4;k++) dst[((size_t)b*NH+h)*NS + s + k] = acc[h][k];
    }
  }
}

// K4: unnormalized pv partials with on-the-fly exp (sums the 4 score quarters).
// Grid (4 e-chunks, SC=64, NB) = 512 blocks, 256 thr = 4 head-groups x 64 e4.
__global__ void __launch_bounds__(256) k_pv(const float* __restrict__ embV){
  int ec = blockIdx.x, sc = blockIdx.y, b = blockIdx.z;
  __shared__ float ps[NH][SCLEN];      // 2 KB
  int tid = threadIdx.x;
  int s0 = sc*SCLEN;
  if (tid < 128){
    int h = tid >> 3;                  // 8 float4 per head row (32 s)
    int s4 = tid & 7;
    size_t base = ((size_t)b*NH+h)*512 + sc*8 + s4;   // float4 index into [b][h][s]
    const float4* p4 = (const float4*)g_p;
    float4 r0 = p4[base];
    float4 r1 = p4[base + (size_t)NB*NH*512];
    float4 r2 = p4[base + (size_t)2*NB*NH*512];
    float4 r3 = p4[base + (size_t)3*NB*NH*512];
    float4 e;
    e.x = __expf(r0.x+r1.x+r2.x+r3.x);
    e.y = __expf(r0.y+r1.y+r2.y+r3.y);
    e.z = __expf(r0.z+r1.z+r2.z+r3.z);
    e.w = __expf(r0.w+r1.w+r2.w+r3.w);
    ((float4*)ps[h])[s4] = e;
  }
  __syncthreads();
  if (ec == 0 && tid < NH){
    float su = 0.f;
#pragma unroll
    for (int ss=0; ss<SCLEN; ++ss) su += ps[tid][ss];
    g_sump[((size_t)b*SC + sc)*NH + tid] = su;
  }
  int hg = tid >> 6;                   // head group 0..3 (4 heads each)
  int t64 = tid & 63;
  int e4 = ec*64 + t64;
  int h0 = hg*4;
  const float4* v = (const float4*)(embV + ((size_t)b*NS + s0)*NE) + e4;
  float4 acc[4];
#pragma unroll
  for (int j=0;j<4;j++) acc[j] = make_float4(0.f,0.f,0.f,0.f);
#pragma unroll 8
  for (int ss=0; ss<SCLEN; ++ss){
    float4 x = v[(size_t)ss*256];
#pragma unroll
    for (int j=0;j<4;j++){
      float pw = ps[h0+j][ss];
      acc[j].x = fmaf(pw,x.x,acc[j].x);
      acc[j].y = fmaf(pw,x.y,acc[j].y);
      acc[j].z = fmaf(pw,x.z,acc[j].z);
      acc[j].w = fmaf(pw,x.w,acc[j].w);
    }
  }
  float4* outp = (float4*)g_pvp + ((size_t)(b*SC + sc)*NH)*256 + e4;
#pragma unroll
  for (int j=0;j<4;j++) outp[(h0+j)*256] = acc[j];
}

// K5: reduce pv partials over SC chunks. 256 blocks x 32 threads.
__global__ void __launch_bounds__(32) k_pvred(){
  int i4 = blockIdx.x*32 + threadIdx.x;    // over NB*NH*NE/4 = 8192
  int b = i4 >> 12;
  int r = i4 & 4095;
  const float4* src = (const float4*)g_pvp + (size_t)b*SC*4096 + r;
  float4 acc = make_float4(0.f,0.f,0.f,0.f);
#pragma unroll 8
  for (int c=0;c<SC;c++){
    float4 x = src[(size_t)c*4096];
    acc.x+=x.x; acc.y+=x.y; acc.z+=x.z; acc.w+=x.w;
  }
  ((float4*)g_pv)[i4] = acc;
}

// K6: g_o[b][i] = dot(g_pv[b][h_i][:], Wv[i][:]) / rowsum[b][h_i]  (256 blocks)
__global__ void k_o(const float* __restrict__ Wv){
  int gw = (blockIdx.x*blockDim.x + threadIdx.x) >> 5;
  int lane = threadIdx.x & 31;
  int b = gw >> 10, i = gw & 1023;
  int h = i >> 6;
  float sp = g_sump[((size_t)b*SC + lane)*NH + h]
           + g_sump[((size_t)b*SC + lane + 32)*NH + h];
  float ssum = warp_sum(sp);
  const float4* xr = (const float4*)(g_pv + ((size_t)b*NH + h)*NE);
  const float4* wr = (const float4*)(Wv + (size_t)i*NE);
  float acc = 0.f;
#pragma unroll
  for (int it=0; it<8; ++it) acc += dot4(xr[lane+it*32], wr[lane+it*32]);
  acc = warp_sum(acc);
  if (!lane) g_o[b*NE+i] = acc / ssum;
}

// K7: g_y[b][j] = dot(g_o[b][:], Wo[j][:])  (256 blocks)
__global__ void k_y(const float* __restrict__ Wo){
  int gw = (blockIdx.x*blockDim.x + threadIdx.x) >> 5;
  int lane = threadIdx.x & 31;
  int b = gw >> 10, j = gw & 1023;
  const float4* xr = (const float4*)(g_o + (size_t)b*NE);
  const float4* wr = (const float4*)(Wo + (size_t)j*NE);
  float acc = 0.f;
#pragma unroll
  for (int it=0; it<8; ++it) acc += dot4(xr[lane+it*32], wr[lane+it*32]);
  acc = warp_sum(acc);
  if (!lane) g_y[b*NE+j] = acc;
}

// K8: broadcast y row to all S positions (4096 blocks, store-bound)
__global__ void k_bcast(float* __restrict__ out){
  int gi = blockIdx.x*blockDim.x + threadIdx.x;  // float4 idx over NB*NS*NE/4
  int e4 = gi & 255;
  int b  = gi >> 19;                              // / (NS*NE/4)
  float4 y = ((const float4*)g_y)[b*256 + e4];
  ((float4*)out)[gi] = y;
}

extern "C" void kernel_launch(void* const* d_in, const int* in_sizes, int n_in,
                              void* d_out, int out_size){
  const float* inputs = (const float*)d_in[0];
  const float* embV   = (const float*)d_in[1];
  const float* embK   = (const float*)d_in[2];
  const float* Wq     = (const float*)d_in[3];
  const float* Wk     = (const float*)d_in[4];
  const float* Wv     = (const float*)d_in[5];
  const float* Wo     = (const float*)d_in[6];
  float* out = (float*)d_out;

  k_q      <<<256, 256>>>(inputs, Wq);
  k_qwk    <<<dim3(64, NB), 64>>>(Wk);
  k_scores <<<dim3(NS/32, NQ, NB), 256>>>(embK);
  k_pv     <<<dim3(4, SC, NB), 256>>>(embV);
  k_pvred  <<<256, 32>>>();
  k_o      <<<256, 256>>>(Wv);
  k_y      <<<256, 256>>>(Wo);
  k_bcast  <<<(NB*NS*NE/4)/256, 256>>>(out);
}

// round 7
// speedup vs baseline: 1.0808x; 1.0808x over previous
#include <cuda_runtime.h>

#define NB 2
#define NS 2048
#define NE 1024
#define NH 16
#define ND 64
#define SC 64       // s-chunks for pv partials
#define SCLEN 32    // s per chunk (SC*SCLEN == NS)
#define NQ 4        // e-quarters for score partials

// Scratch (allocation-free: device globals)
__device__ float g_q[NB*NE];
__device__ float g_qwk[NB*NH*NE];        // [b][h][e]
__device__ float g_p[NQ*NB*NH*NS];       // raw score partials [q][b][h][s]
__device__ float g_pvp[NB*SC*NH*NE];     // unnormalized pv partials [b][sc][h][e] (8 MB)
__device__ float g_sump[NB*SC*NH];       // per-chunk exp sums
__device__ float g_pv[NB*NH*NE];
__device__ float g_o[NB*NE];
__device__ float g_y[NB*NE];

__device__ __forceinline__ float dot4(float4 a, float4 b){
  return fmaf(a.x,b.x, fmaf(a.y,b.y, fmaf(a.z,b.z, a.w*b.w)));
}
__device__ __forceinline__ float warp_sum(float v){
#pragma unroll
  for (int o=16;o>0;o>>=1) v += __shfl_xor_sync(0xffffffffu, v, o);
  return v;
}

// K1: g_q[b][j] = dot(inputs[b, S-1, :], Wq[j, :])  (warp per output, 256 blocks)
__global__ void k_q(const float* __restrict__ inputs, const float* __restrict__ Wq){
  int gw = (blockIdx.x*blockDim.x + threadIdx.x) >> 5;
  int lane = threadIdx.x & 31;
  int b = gw >> 10, j = gw & 1023;
  const float4* xr = (const float4*)(inputs + ((size_t)b*NS + (NS-1))*NE);
  const float4* wr = (const float4*)(Wq + (size_t)j*NE);
  float acc = 0.f;
#pragma unroll
  for (int it=0; it<8; ++it) acc += dot4(xr[lane+it*32], wr[lane+it*32]);
  acc = warp_sum(acc);
  if (!lane) g_q[b*NE+j] = acc;
}

// K2: g_qwk[b][h][e] = sum_d g_q[b][h*64+d] * Wk[h*64+d][e]
__global__ void __launch_bounds__(64) k_qwk(const float* __restrict__ Wk){
  int h = blockIdx.x >> 2, eq = blockIdx.x & 3, b = blockIdx.y;
  __shared__ float qs[ND];
  int t = threadIdx.x;
  qs[t] = g_q[b*NE + h*ND + t];
  __syncthreads();
  int e4 = eq*64 + t;
  const float4* Wk4 = (const float4*)Wk;
  float4 a = make_float4(0.f,0.f,0.f,0.f);
#pragma unroll 8
  for (int d=0; d<ND; ++d){
    float qv = qs[d];
    float4 w = Wk4[(size_t)(h*ND + d)*256 + e4];
    a.x = fmaf(qv,w.x,a.x); a.y = fmaf(qv,w.y,a.y);
    a.z = fmaf(qv,w.z,a.z); a.w = fmaf(qv,w.w,a.w);
  }
  ((float4*)g_qwk)[(size_t)(b*NH + h)*256 + e4] = a;
}

// K3: score e-quarter partials.
// Grid (NS/32, NQ, NB) = 512 blocks. Block 256 thr = 8 warps x 4 s-rows.
// g_p[q][b][h][s] = dot(embK[b,s,eq*256:(eq+1)*256], qwk[b,h,same])
__global__ void __launch_bounds__(256) k_scores(const float* __restrict__ embK){
  __shared__ float4 qwk_s[NH*64];      // 16 KB e-quarter
  int eq = blockIdx.y, b = blockIdx.z;
  {
    const float4* src = (const float4*)g_qwk + (size_t)b*NH*256 + eq*64;
#pragma unroll
    for (int i=0;i<4;i++){
      int idx = threadIdx.x + i*256;   // over 1024 = 16h x 64f4
      int h = idx >> 6, f4 = idx & 63;
      qwk_s[idx] = src[(size_t)h*256 + f4];
    }
  }
  __syncthreads();
  int wid = threadIdx.x >> 5, lane = threadIdx.x & 31;
  int s = blockIdx.x*32 + wid*4;
  const float4* r = (const float4*)(embK + ((size_t)b*NS + s)*NE) + eq*64;
  float acc[NH][4];
#pragma unroll
  for (int h=0;h<NH;h++){
#pragma unroll
    for (int k=0;k<4;k++) acc[h][k]=0.f;
  }
#pragma unroll
  for (int it=0; it<2; ++it){
    int e4 = lane + it*32;
    float4 x0 = r[e4];
    float4 x1 = r[e4 + 256];
    float4 x2 = r[e4 + 512];
    float4 x3 = r[e4 + 768];
#pragma unroll
    for (int h=0; h<NH; ++h){
      float4 w = qwk_s[h*64 + e4];
      acc[h][0] += dot4(x0,w);
      acc[h][1] += dot4(x1,w);
      acc[h][2] += dot4(x2,w);
      acc[h][3] += dot4(x3,w);
    }
  }
#pragma unroll
  for (int h=0;h<NH;h++){
#pragma unroll
    for (int k=0;k<4;k++) acc[h][k] = warp_sum(acc[h][k]);
  }
  if (!lane){
    float* dst = g_p + (size_t)eq*NB*NH*NS;
#pragma unroll
    for (int h=0;h<NH;h++){
#pragma unroll
      for (int k=0;k<4;k++) dst[((size_t)b*NH+h)*NS + s + k] = acc[h][k];
    }
  }
}

// K4: unnormalized pv partials with on-the-fly exp (sums the 4 score quarters).
// Grid (4 e-chunks, SC=64, NB) = 512 blocks, 256 thr = 4 head-groups x 64 e4.
__global__ void __launch_bounds__(256) k_pv(const float* __restrict__ embV){
  int ec = blockIdx.x, sc = blockIdx.y, b = blockIdx.z;
  __shared__ float ps[NH][SCLEN];      // 2 KB
  int tid = threadIdx.x;
  int s0 = sc*SCLEN;
  if (tid < 128){
    int h = tid >> 3;                  // 8 float4 per head row (32 s)
    int s4 = tid & 7;
    size_t base = ((size_t)b*NH+h)*512 + sc*8 + s4;   // float4 index into [b][h][s]
    const float4* p4 = (const float4*)g_p;
    float4 r0 = p4[base];
    float4 r1 = p4[base + (size_t)NB*NH*512];
    float4 r2 = p4[base + (size_t)2*NB*NH*512];
    float4 r3 = p4[base + (size_t)3*NB*NH*512];
    float4 e;
    e.x = __expf(r0.x+r1.x+r2.x+r3.x);
    e.y = __expf(r0.y+r1.y+r2.y+r3.y);
    e.z = __expf(r0.z+r1.z+r2.z+r3.z);
    e.w = __expf(r0.w+r1.w+r2.w+r3.w);
    ((float4*)ps[h])[s4] = e;
  }
  __syncthreads();
  if (ec == 0 && tid < NH){
    float su = 0.f;
#pragma unroll
    for (int ss=0; ss<SCLEN; ++ss) su += ps[tid][ss];
    g_sump[((size_t)b*SC + sc)*NH + tid] = su;
  }
  int hg = tid >> 6;                   // head group 0..3 (4 heads each)
  int t64 = tid & 63;
  int e4 = ec*64 + t64;
  int h0 = hg*4;
  const float4* v = (const float4*)(embV + ((size_t)b*NS + s0)*NE) + e4;
  float4 acc[4];
#pragma unroll
  for (int j=0;j<4;j++) acc[j] = make_float4(0.f,0.f,0.f,0.f);
#pragma unroll 8
  for (int ss=0; ss<SCLEN; ++ss){
    float4 x = v[(size_t)ss*256];
#pragma unroll
    for (int j=0;j<4;j++){
      float pw = ps[h0+j][ss];
      acc[j].x = fmaf(pw,x.x,acc[j].x);
      acc[j].y = fmaf(pw,x.y,acc[j].y);
      acc[j].z = fmaf(pw,x.z,acc[j].z);
      acc[j].w = fmaf(pw,x.w,acc[j].w);
    }
  }
  float4* outp = (float4*)g_pvp + ((size_t)(b*SC + sc)*NH)*256 + e4;
#pragma unroll
  for (int j=0;j<4;j++) outp[(h0+j)*256] = acc[j];
}

// K5: reduce pv partials over SC chunks. 256 blocks x 32 threads.
__global__ void __launch_bounds__(32) k_pvred(){
  int i4 = blockIdx.x*32 + threadIdx.x;    // over NB*NH*NE/4 = 8192
  int b = i4 >> 12;
  int r = i4 & 4095;
  const float4* src = (const float4*)g_pvp + (size_t)b*SC*4096 + r;
  float4 acc = make_float4(0.f,0.f,0.f,0.f);
#pragma unroll 8
  for (int c=0;c<SC;c++){
    float4 x = src[(size_t)c*4096];
    acc.x+=x.x; acc.y+=x.y; acc.z+=x.z; acc.w+=x.w;
  }
  ((float4*)g_pv)[i4] = acc;
}

// K6: g_o[b][i] = dot(g_pv[b][h_i][:], Wv[i][:]) / rowsum[b][h_i]  (256 blocks)
__global__ void k_o(const float* __restrict__ Wv){
  int gw = (blockIdx.x*blockDim.x + threadIdx.x) >> 5;
  int lane = threadIdx.x & 31;
  int b = gw >> 10, i = gw & 1023;
  int h = i >> 6;
  float sp = g_sump[((size_t)b*SC + lane)*NH + h]
           + g_sump[((size_t)b*SC + lane + 32)*NH + h];
  float ssum = warp_sum(sp);
  const float4* xr = (const float4*)(g_pv + ((size_t)b*NH + h)*NE);
  const float4* wr = (const float4*)(Wv + (size_t)i*NE);
  float acc = 0.f;
#pragma unroll
  for (int it=0; it<8; ++it) acc += dot4(xr[lane+it*32], wr[lane+it*32]);
  acc = warp_sum(acc);
  if (!lane) g_o[b*NE+i] = acc / ssum;
}

// K7: g_y[b][j] = dot(g_o[b][:], Wo[j][:])  (256 blocks)
__global__ void k_y(const float* __restrict__ Wo){
  int gw = (blockIdx.x*blockDim.x + threadIdx.x) >> 5;
  int lane = threadIdx.x & 31;
  int b = gw >> 10, j = gw & 1023;
  const float4* xr = (const float4*)(g_o + (size_t)b*NE);
  const float4* wr = (const float4*)(Wo + (size_t)j*NE);
  float acc = 0.f;
#pragma unroll
  for (int it=0; it<8; ++it) acc += dot4(xr[lane+it*32], wr[lane+it*32]);
  acc = warp_sum(acc);
  if (!lane) g_y[b*NE+j] = acc;
}

// K8: broadcast y row to all S positions (4096 blocks, store-bound)
__global__ void k_bcast(float* __restrict__ out){
  int gi = blockIdx.x*blockDim.x + threadIdx.x;  // float4 idx over NB*NS*NE/4
  int e4 = gi & 255;
  int b  = gi >> 19;                              // / (NS*NE/4)
  float4 y = ((const float4*)g_y)[b*256 + e4];
  ((float4*)out)[gi] = y;
}

extern "C" void kernel_launch(void* const* d_in, const int* in_sizes, int n_in,
                              void* d_out, int out_size){
  const float* inputs = (const float*)d_in[0];
  const float* embV   = (const float*)d_in[1];
  const float* embK   = (const float*)d_in[2];
  const float* Wq     = (const float*)d_in[3];
  const float* Wk     = (const float*)d_in[4];
  const float* Wv     = (const float*)d_in[5];
  const float* Wo     = (const float*)d_in[6];
  float* out = (float*)d_out;

  k_q      <<<256, 256>>>(inputs, Wq);
  k_qwk    <<<dim3(64, NB), 64>>>(Wk);
  k_scores <<<dim3(NS/32, NQ, NB), 256>>>(embK);
  k_pv     <<<dim3(4, SC, NB), 256>>>(embV);
  k_pvred  <<<256, 32>>>();
  k_o      <<<256, 256>>>(Wv);
  k_y      <<<256, 256>>>(Wo);
  k_bcast  <<<(NB*NS*NE/4)/256, 256>>>(out);
}